// round 16
// baseline (speedup 1.0000x reference)
#include <cuda_runtime.h>
#include <cuda_fp16.h>
#include <cstdint>

#define BB 2048
#define TT 2
#define NTOK 49
#define NHEAD 16
#define HDIM 32
#define CDIM 512
#define NN2 (NTOK*NTOK)

// ---------------- scratch (device globals; no allocs allowed) ----------------
// GEMM operand arrays live in "chunked" layout: [rows/128][16][128*32 halves],
// each 8KB block contiguous + SW64-swizzled (so cp.async.bulk can load it raw).
__device__ __align__(16) unsigned short g_xh[(size_t)BB*NTOK*CDIM],    g_xl[(size_t)BB*NTOK*CDIM];
__device__ __align__(16) unsigned short g_mh[(size_t)BB*TT*NTOK*CDIM], g_ml[(size_t)BB*TT*NTOK*CDIM];
__device__ __align__(16) unsigned short g_oh[(size_t)BB*TT*NTOK*CDIM], g_ol[(size_t)BB*TT*NTOK*CDIM];
__device__ __align__(16) unsigned short g_qwh[CDIM*CDIM],    g_qwl[CDIM*CDIM];
__device__ __align__(16) unsigned short g_kvwh[2*CDIM*CDIM], g_kvwl[2*CDIM*CDIM];
__device__ __align__(16) unsigned short g_pwh[CDIM*CDIM],    g_pwl[CDIM*CDIM];
__device__ float g_q [(size_t)BB*NTOK*CDIM];
__device__ float g_kv[(size_t)BB*TT*NTOK*2*CDIM];
__device__ float g_bias[NHEAD*NN2];

// chunked-layout byte offset for element (row m, col k), K=512, swizzled
__device__ __forceinline__ size_t coff(int m, int k){
    unsigned inner = ((unsigned)(m & 127) << 6) + (((unsigned)k & 31) << 1);
    inner ^= (inner >> 3) & 0x30u;
    return ((size_t)(m >> 7) * 16 + (unsigned)(k >> 5)) * 8192 + inner;
}

// ---------------- PTX helpers (base-target only: sm_90-era features) ----------
__device__ __forceinline__ uint32_t smem_u32(const void* p){
    uint32_t a;
    asm("{ .reg .u64 t; cvta.to.shared.u64 t, %1; cvt.u32.u64 %0, t; }":"=r"(a):"l"(p));
    return a;
}
#define CP_BULK(dst, src, mbar) \
    asm volatile("cp.async.bulk.shared::cta.global.mbarrier::complete_tx::bytes [%0], [%1], %2, [%3];" \
        :: "r"((uint32_t)(dst)), "l"(src), "r"(8192u), "r"((uint32_t)(mbar)) : "memory")
#define MB_INIT(a,c) asm volatile("mbarrier.init.shared.b64 [%0], %1;"::"r"((uint32_t)(a)),"r"((uint32_t)(c)):"memory")
#define MB_EXPECT(a,tx) asm volatile("mbarrier.arrive.expect_tx.shared.b64 _, [%0], %1;"::"r"((uint32_t)(a)),"r"((uint32_t)(tx)):"memory")
#define MB_WAIT(a,p) do{ uint32_t _m=(uint32_t)(a),_p=(uint32_t)(p),_d; \
    asm volatile("{\n\t.reg .pred q;\n\tmbarrier.try_wait.parity.acquire.cta.shared::cta.b64 q, [%1], %2;\n\tselp.b32 %0,1,0,q;\n\t}":"=r"(_d):"r"(_m),"r"(_p):"memory"); \
    if(!_d){ asm volatile("{\n\t.reg .pred P;\n\tWL_%=:\n\tmbarrier.try_wait.parity.acquire.cta.shared::cta.b64 P, [%0], %1, 0x989680;\n\t@P bra.uni WD_%=;\n\tbra.uni WL_%=;\n\tWD_%=:\n\t}"::"r"(_m),"r"(_p):"memory"); } }while(0)
#define FENCE_ASY() asm volatile("fence.proxy.async.shared::cta;":::"memory")

__device__ __forceinline__ void ldsm4(uint32_t* r, uint32_t addr){
    asm volatile("ldmatrix.sync.aligned.m8n8.x4.shared.b16 {%0,%1,%2,%3}, [%4];"
        : "=r"(r[0]),"=r"(r[1]),"=r"(r[2]),"=r"(r[3]) : "r"(addr));
}
__device__ __forceinline__ void mma16816(float* d, const uint32_t* a, const uint32_t* b){
    asm volatile("mma.sync.aligned.m16n8k16.row.col.f32.f16.f16.f32 "
        "{%0,%1,%2,%3}, {%4,%5,%6,%7}, {%8,%9}, {%0,%1,%2,%3};"
        : "+f"(d[0]),"+f"(d[1]),"+f"(d[2]),"+f"(d[3])
        : "r"(a[0]),"r"(a[1]),"r"(a[2]),"r"(a[3]), "r"(b[0]),"r"(b[1]));
}

// ---------------- f32x2 packed-FMA helpers (Blackwell FFMA2) ----------------
__device__ __forceinline__ unsigned long long pack2(float a){
    unsigned long long r;
    unsigned int ai = __float_as_uint(a);
    asm("mov.b64 %0, {%1, %1};" : "=l"(r) : "r"(ai));
    return r;
}
__device__ __forceinline__ void fma2(unsigned long long& c,
                                     unsigned long long a,
                                     unsigned long long b){
    asm("fma.rn.f32x2 %0, %1, %2, %3;" : "=l"(c) : "l"(a), "l"(b), "l"(c));
}
__device__ __forceinline__ float2 unpack2(unsigned long long p){
    unsigned int lo, hi;
    asm("mov.b64 {%0, %1}, %2;" : "=r"(lo), "=r"(hi) : "l"(p));
    return make_float2(__uint_as_float(lo), __uint_as_float(hi));
}

// ---------------- fp32 -> fp16 hi/lo split into chunked layout ----------------
__global__ void split_kernel(const float* __restrict__ in,
                             unsigned short* __restrict__ hi,
                             unsigned short* __restrict__ lo, long long n4){
    long long i = (long long)blockIdx.x*256 + threadIdx.x;
    if (i >= n4) return;
    int m  = (int)(i >> 7);          // 128 float4 per row
    int k4 = (int)(i & 127);
    float4 v = reinterpret_cast<const float4*>(in)[i];
    float vs[4] = {v.x, v.y, v.z, v.w};
    unsigned short hb[4], lb[4];
#pragma unroll
    for (int c = 0; c < 4; c++){
        __half h = __float2half_rn(vs[c]);
        float r = vs[c] - __half2float(h);
        hb[c] = __half_as_ushort(h);
        lb[c] = __half_as_ushort(__float2half_rn(r));
    }
    uint2 H, L;
    H.x = hb[0] | ((uint32_t)hb[1] << 16);  H.y = hb[2] | ((uint32_t)hb[3] << 16);
    L.x = lb[0] | ((uint32_t)lb[1] << 16);  L.y = lb[2] | ((uint32_t)lb[3] << 16);
    size_t off = coff(m, k4 << 2);   // 8B-aligned; swizzle preserves 8B units
    *reinterpret_cast<uint2*>((char*)hi + off) = H;
    *reinterpret_cast<uint2*>((char*)lo + off) = L;
}

// ---------------- bias gather ----------------
__global__ void bias_gather_kernel(const float* __restrict__ rpb,
                                   const int* __restrict__ rel){
    int g = blockIdx.x*256 + threadIdx.x;
    if (g >= NHEAD*NN2) return;
    int h = g / NN2, p = g - h*NN2;
    g_bias[g] = rpb[rel[p]*NHEAD + h];
}

// ---------------- warp-MMA GEMM, bulk-DMA loads (R15 winner, frozen) ---------
#define NSTAGE 4
#define GEMM_SMEM (NSTAGE*16384 + 64)
#define NCHUNK 32

__global__ __launch_bounds__(256, 2)
void gemm_mma(const unsigned short* __restrict__ Ah, const unsigned short* __restrict__ Al,
              const unsigned short* __restrict__ Wh,
              const float* __restrict__ bias, float* __restrict__ C, int N, float alpha){
    extern __shared__ __align__(128) unsigned char dyn[];
    const uint32_t base = smem_u32(dyn);
    const uint32_t mb0  = base + NSTAGE*16384;          // 4 mbarriers, 8B apart

    const int tid = threadIdx.x, lane = tid & 31, wid = tid >> 5;
    const int wm = wid & 1, wn = wid >> 1;              // 2 x 4 warp grid
    const int m0 = blockIdx.y * 128, n0 = blockIdx.x * 128;

    const char* AP[2] = {(const char*)Ah, (const char*)Al};

    if (tid == 0){
#pragma unroll
        for (int s = 0; s < NSTAGE; s++) MB_INIT(mb0 + s*8, 1);
        FENCE_ASY();
    }
    __syncthreads();

    auto issue_chunk = [&](int t, int s){               // thread 0 only
        const char* srcA = AP[t >> 4] + ((size_t)blockIdx.y*16 + (t & 15))*8192;
        const char* srcW = (const char*)Wh + ((size_t)blockIdx.x*16 + (t & 15))*8192;
        uint32_t bar = mb0 + s*8;
        MB_EXPECT(bar, 16384u);
        CP_BULK(base + s*16384,        srcA, bar);
        CP_BULK(base + s*16384 + 8192, srcW, bar);
    };
    if (tid == 0){ issue_chunk(0,0); issue_chunk(1,1); issue_chunk(2,2); }

    // lane offsets within an 8KB block (64B rows, SW64 swizzle)
    uint32_t a_off[4], a_msk[4], b_off[2], b_msk[2];
#pragma unroll
    for (int mt = 0; mt < 4; mt++){
        int r = wm*64 + mt*16 + (lane & 15);
        a_off[mt] = (uint32_t)(r*64 + ((lane >> 4) & 1)*16);
        a_msk[mt] = (uint32_t)(((r >> 1) & 3) << 4);
    }
    {
        int g = lane >> 3;
#pragma unroll
        for (int q = 0; q < 2; q++){
            int r = wn*32 + (2*q + (g >> 1))*8 + (lane & 7);
            b_off[q] = (uint32_t)(r*64 + (g & 1)*16);
            b_msk[q] = (uint32_t)(((r >> 1) & 3) << 4);
        }
    }

    float acc[4][4][4];
#pragma unroll
    for (int i = 0; i < 4; i++)
#pragma unroll
        for (int j = 0; j < 4; j++)
#pragma unroll
            for (int k = 0; k < 4; k++) acc[i][j][k] = 0.f;

    for (int t = 0; t < NCHUNK; ++t){
        const int s = t & (NSTAGE - 1);
        const uint32_t ab = base + s*16384;
        const uint32_t wb = ab + 8192;
        MB_WAIT(mb0 + s*8, (t >> 2) & 1);

#pragma unroll
        for (int ks = 0; ks < 2; ks++){                  // 2 x k16 within BK=32
            uint32_t af[4][4], bf[2][4];
#pragma unroll
            for (int mt = 0; mt < 4; mt++)
                ldsm4(af[mt], ab + ((a_off[mt] + ks*32) ^ a_msk[mt]));
#pragma unroll
            for (int q = 0; q < 2; q++)
                ldsm4(bf[q],  wb + ((b_off[q] + ks*32) ^ b_msk[q]));
#pragma unroll
            for (int mt = 0; mt < 4; mt++){
                mma16816(acc[mt][0], af[mt], bf[0] + 0);
                mma16816(acc[mt][1], af[mt], bf[0] + 2);
                mma16816(acc[mt][2], af[mt], bf[1] + 0);
                mma16816(acc[mt][3], af[mt], bf[1] + 2);
            }
        }
        __syncthreads();                                 // all reads of stage (t+3)&3 done
        if (t + 3 < NCHUNK && tid == 0) issue_chunk(t + 3, (t + 3) & (NSTAGE - 1));
    }

    // epilogue
#pragma unroll
    for (int mt = 0; mt < 4; mt++){
#pragma unroll
        for (int nt = 0; nt < 4; nt++){
            int rg = m0 + wm*64 + mt*16 + (lane >> 2);
            int cg = n0 + wn*32 + nt*8 + 2*(lane & 3);
            float b0 = bias[cg], b1 = bias[cg + 1];
            float2 o0 = make_float2(alpha*(acc[mt][nt][0] + b0), alpha*(acc[mt][nt][1] + b1));
            float2 o1 = make_float2(alpha*(acc[mt][nt][2] + b0), alpha*(acc[mt][nt][3] + b1));
            *reinterpret_cast<float2*>(C + (size_t)rg*N + cg)       = o0;
            *reinterpret_cast<float2*>(C + (size_t)(rg + 8)*N + cg) = o1;
        }
    }
}

// ---------------- attention: FFMA2 4x4 register-blocked ----------
#define QP 36
#define SP 56

__global__ __launch_bounds__(128)
void attn_kernel(){
    const int bh = blockIdx.x;
    const int h  = bh & (NHEAD-1);
    const int bt = bh >> 4;
    const int b  = bt >> 1;
    __shared__ __align__(16) float sq[52*QP], sk[52*QP], sv[52*QP], sS[52*SP];
    const int tid = threadIdx.x;

    for (int p = tid; p < 52*HDIM; p += 128){
        int i = p >> 5, d = p & 31;
        float qv = 0.f, kv = 0.f, vv = 0.f;
        if (i < NTOK){
            qv = g_q[(size_t)(b*NTOK+i)*CDIM + h*HDIM + d];
            const float* kvr = g_kv + (size_t)(bt*NTOK+i)*(2*CDIM) + h*HDIM + d;
            kv = kvr[0];
            vv = kvr[CDIM];
        }
        sq[i*QP+d] = qv;
        sk[i*QP+d] = kv;
        sv[i*QP+d] = vv;
    }
    __syncthreads();

    // scores + bias: accumulate over d-pairs with packed f32x2 FMA
    const float* biasH = g_bias + h*NN2;
    for (int p = tid; p < 169; p += 128){
        int ti = p / 13, tj = p - ti*13;
        int i0 = ti*4, j0 = tj*4;
        unsigned long long a2[4][4];
#pragma unroll
        for (int r = 0; r < 4; r++)
#pragma unroll
            for (int c = 0; c < 4; c++) a2[r][c] = 0ull;
#pragma unroll
        for (int dd = 0; dd < 8; dd++){
            ulonglong2 qa[4], kb[4];
#pragma unroll
            for (int r = 0; r < 4; r++) qa[r] = *reinterpret_cast<const ulonglong2*>(&sq[(i0+r)*QP + dd*4]);
#pragma unroll
            for (int c = 0; c < 4; c++) kb[c] = *reinterpret_cast<const ulonglong2*>(&sk[(j0+c)*QP + dd*4]);
#pragma unroll
            for (int r = 0; r < 4; r++)
#pragma unroll
                for (int c = 0; c < 4; c++){
                    fma2(a2[r][c], qa[r].x, kb[c].x);
                    fma2(a2[r][c], qa[r].y, kb[c].y);
                }
        }
#pragma unroll
        for (int r = 0; r < 4; r++)
#pragma unroll
            for (int c = 0; c < 4; c++){
                int i = i0 + r, j = j0 + c;
                float2 t = unpack2(a2[r][c]);
                float bv = (i < NTOK && j < NTOK) ? biasH[i*NTOK + j] : 0.f;
                sS[i*SP + j] = t.x + t.y + bv;
            }
    }
    __syncthreads();

    const int warp = tid >> 5, lane = tid & 31;
    for (int i = warp; i < NTOK; i += 4){
        float* row = sS + i*SP;
        float x0 = row[lane];
        bool  v1 = (lane + 32) < NTOK;
        float x1 = v1 ? row[lane+32] : -3.402823466e38f;
        float m = fmaxf(x0, x1);
#pragma unroll
        for (int o = 16; o > 0; o >>= 1) m = fmaxf(m, __shfl_xor_sync(0xffffffffu, m, o));
        float e0 = __expf(x0 - m);
        float e1 = v1 ? __expf(x1 - m) : 0.f;
        float s = e0 + e1;
#pragma unroll
        for (int o = 16; o > 0; o >>= 1) s += __shfl_xor_sync(0xffffffffu, s, o);
        float inv = 1.0f / s;
        row[lane] = e0*inv;
        if (v1) row[lane+32] = e1*inv;
    }
    __syncthreads();

    // O = S @ v : m in groups of 4 (float4 S loads), d-pairs packed f32x2.
    // m runs to 52: sv rows 49..51 are zero, so padded-S columns contribute 0.
    for (int p = tid; p < 104; p += 128){
        int ti = p >> 3, td = p & 7;
        int i0 = ti*4, d0 = td*4;
        unsigned long long acc2[4][2];
#pragma unroll
        for (int r = 0; r < 4; r++){ acc2[r][0] = 0ull; acc2[r][1] = 0ull; }
        for (int m4 = 0; m4 < 52; m4 += 4){
            float4 sr[4];
            ulonglong2 vr[4];
#pragma unroll
            for (int r = 0; r < 4; r++)  sr[r]  = *reinterpret_cast<const float4*>(&sS[(i0+r)*SP + m4]);
#pragma unroll
            for (int mm = 0; mm < 4; mm++) vr[mm] = *reinterpret_cast<const ulonglong2*>(&sv[(m4+mm)*QP + d0]);
#pragma unroll
            for (int mm = 0; mm < 4; mm++){
                const float* s0 = reinterpret_cast<const float*>(&sr[0]);
                const float* s1 = reinterpret_cast<const float*>(&sr[1]);
                const float* s2 = reinterpret_cast<const float*>(&sr[2]);
                const float* s3 = reinterpret_cast<const float*>(&sr[3]);
                unsigned long long p0 = pack2(s0[mm]);
                unsigned long long p1 = pack2(s1[mm]);
                unsigned long long p2 = pack2(s2[mm]);
                unsigned long long p3 = pack2(s3[mm]);
                fma2(acc2[0][0], p0, vr[mm].x); fma2(acc2[0][1], p0, vr[mm].y);
                fma2(acc2[1][0], p1, vr[mm].x); fma2(acc2[1][1], p1, vr[mm].y);
                fma2(acc2[2][0], p2, vr[mm].x); fma2(acc2[2][1], p2, vr[mm].y);
                fma2(acc2[3][0], p3, vr[mm].x); fma2(acc2[3][1], p3, vr[mm].y);
            }
        }
#pragma unroll
        for (int r = 0; r < 4; r++){
            int i = i0 + r;
            if (i >= NTOK) break;
            float2 lo = unpack2(acc2[r][0]);
            float2 hi2 = unpack2(acc2[r][1]);
            float av[4] = {lo.x, lo.y, hi2.x, hi2.y};
            int m = bt*NTOK + i;
            int k = h*HDIM + d0;
            unsigned short hb[4], lb[4];
#pragma unroll
            for (int c = 0; c < 4; c++){
                __half hh = __float2half_rn(av[c]);
                hb[c] = __half_as_ushort(hh);
                lb[c] = __half_as_ushort(__float2half_rn(av[c] - __half2float(hh)));
            }
            uint2 H, L;
            H.x = hb[0] | ((uint32_t)hb[1] << 16);  H.y = hb[2] | ((uint32_t)hb[3] << 16);
            L.x = lb[0] | ((uint32_t)lb[1] << 16);  L.y = lb[2] | ((uint32_t)lb[3] << 16);
            size_t off = coff(m, k);
            *reinterpret_cast<uint2*>((char*)g_oh + off) = H;
            *reinterpret_cast<uint2*>((char*)g_ol + off) = L;
        }
    }
}

// ---------------- launch ----------------
extern "C" void kernel_launch(void* const* d_in, const int* in_sizes, int n_in,
                              void* d_out, int out_size){
    const float* x      = (const float*)d_in[0];
    const float* memory = (const float*)d_in[1];
    const float* rpb    = (const float*)d_in[2];
    const float* q_w    = (const float*)d_in[3];
    const float* q_b    = (const float*)d_in[4];
    const float* kv_w   = (const float*)d_in[5];
    const float* kv_b   = (const float*)d_in[6];
    const float* proj_w = (const float*)d_in[7];
    const float* proj_b = (const float*)d_in[8];
    const int*   rel    = (const int*)d_in[9];
    float* out = (float*)d_out;

    unsigned short *xh,*xl,*mh,*ml,*oh,*ol,*qwh,*qwl,*kvwh,*kvwl,*pwh,*pwl;
    float *pq,*pkv;
    cudaGetSymbolAddress((void**)&xh,g_xh);     cudaGetSymbolAddress((void**)&xl,g_xl);
    cudaGetSymbolAddress((void**)&mh,g_mh);     cudaGetSymbolAddress((void**)&ml,g_ml);
    cudaGetSymbolAddress((void**)&oh,g_oh);     cudaGetSymbolAddress((void**)&ol,g_ol);
    cudaGetSymbolAddress((void**)&qwh,g_qwh);   cudaGetSymbolAddress((void**)&qwl,g_qwl);
    cudaGetSymbolAddress((void**)&kvwh,g_kvwh); cudaGetSymbolAddress((void**)&kvwl,g_kvwl);
    cudaGetSymbolAddress((void**)&pwh,g_pwh);   cudaGetSymbolAddress((void**)&pwl,g_pwl);
    cudaGetSymbolAddress((void**)&pq,g_q);      cudaGetSymbolAddress((void**)&pkv,g_kv);

    cudaFuncSetAttribute(gemm_mma, cudaFuncAttributeMaxDynamicSharedMemorySize, GEMM_SMEM);

    const float scale = 0.17677669529663687f;  // 32^-0.5
    long long n4x = (long long)BB*NTOK*CDIM/4;
    long long n4m = (long long)BB*TT*NTOK*CDIM/4;

    // Launch order keeps gemm_mma(KV) at slot #4 — the ncu window.
    split_kernel<<<(unsigned)((n4m+255)/256),256>>>(memory, mh, ml, n4m);        // #1
    split_kernel<<<(2*CDIM*CDIM/4+255)/256,256>>>(kv_w, kvwh, kvwl, 2*CDIM*CDIM/4); // #2
    split_kernel<<<(unsigned)((n4x+255)/256),256>>>(x, xh, xl, n4x);             // #3
    {   // #4 (PROFILED): KV = memory @ kv_w^T + kv_b   M=200704 N=1024
        dim3 g(2*CDIM/128, BB*TT*NTOK/128);
        gemm_mma<<<g, 256, GEMM_SMEM>>>(mh, ml, kvwh, kv_b, pkv, 2*CDIM, 1.0f);
    }
    split_kernel<<<(CDIM*CDIM/4+255)/256,256>>>(q_w, qwh, qwl, CDIM*CDIM/4);     // #5
    {   // #6: Q = scale*(x @ q_w^T + q_b)              M=100352 N=512
        dim3 g(CDIM/128, BB*NTOK/128);
        gemm_mma<<<g, 256, GEMM_SMEM>>>(xh, xl, qwh, q_b, pq, CDIM, scale);
    }
    split_kernel<<<(CDIM*CDIM/4+255)/256,256>>>(proj_w, pwh, pwl, CDIM*CDIM/4);  // #7
    bias_gather_kernel<<<(NHEAD*NN2 + 255)/256, 256>>>(rpb, rel);                // #8
    attn_kernel<<<BB*TT*NHEAD, 128>>>();                                         // #9
    {   // #10: out = attn @ proj_w^T + proj_b          M=200704 N=512
        dim3 g(CDIM/128, BB*TT*NTOK/128);
        gemm_mma<<<g, 256, GEMM_SMEM>>>(oh, ol, pwh, proj_b, out, CDIM, 1.0f);
    }
    (void)in_sizes; (void)n_in; (void)out_size;
}

// round 17
// speedup vs baseline: 1.0641x; 1.0641x over previous
#include <cuda_runtime.h>
#include <cuda_fp16.h>
#include <cstdint>

#define BB 2048
#define TT 2
#define NTOK 49
#define NHEAD 16
#define HDIM 32
#define CDIM 512
#define NN2 (NTOK*NTOK)

// ---------------- scratch (device globals; no allocs allowed) ----------------
// GEMM operand arrays live in "chunked" layout: [rows/128][16][128*32 halves],
// each 8KB block contiguous + SW64-swizzled (so cp.async.bulk can load it raw).
__device__ __align__(16) unsigned short g_xh[(size_t)BB*NTOK*CDIM],    g_xl[(size_t)BB*NTOK*CDIM];
__device__ __align__(16) unsigned short g_mh[(size_t)BB*TT*NTOK*CDIM], g_ml[(size_t)BB*TT*NTOK*CDIM];
__device__ __align__(16) unsigned short g_oh[(size_t)BB*TT*NTOK*CDIM], g_ol[(size_t)BB*TT*NTOK*CDIM];
__device__ __align__(16) unsigned short g_qwh[CDIM*CDIM],    g_qwl[CDIM*CDIM];
__device__ __align__(16) unsigned short g_kvwh[2*CDIM*CDIM], g_kvwl[2*CDIM*CDIM];
__device__ __align__(16) unsigned short g_pwh[CDIM*CDIM],    g_pwl[CDIM*CDIM];
__device__ float g_q [(size_t)BB*NTOK*CDIM];
__device__ float g_kv[(size_t)BB*TT*NTOK*2*CDIM];
__device__ float g_bias[NHEAD*NN2];

// chunked-layout byte offset for element (row m, col k), K=512, swizzled
__device__ __forceinline__ size_t coff(int m, int k){
    unsigned inner = ((unsigned)(m & 127) << 6) + (((unsigned)k & 31) << 1);
    inner ^= (inner >> 3) & 0x30u;
    return ((size_t)(m >> 7) * 16 + (unsigned)(k >> 5)) * 8192 + inner;
}

// ---------------- PTX helpers (base-target only: sm_90-era features) ----------
__device__ __forceinline__ uint32_t smem_u32(const void* p){
    uint32_t a;
    asm("{ .reg .u64 t; cvta.to.shared.u64 t, %1; cvt.u32.u64 %0, t; }":"=r"(a):"l"(p));
    return a;
}
#define CP_BULK(dst, src, mbar) \
    asm volatile("cp.async.bulk.shared::cta.global.mbarrier::complete_tx::bytes [%0], [%1], %2, [%3];" \
        :: "r"((uint32_t)(dst)), "l"(src), "r"(8192u), "r"((uint32_t)(mbar)) : "memory")
#define MB_INIT(a,c) asm volatile("mbarrier.init.shared.b64 [%0], %1;"::"r"((uint32_t)(a)),"r"((uint32_t)(c)):"memory")
#define MB_EXPECT(a,tx) asm volatile("mbarrier.arrive.expect_tx.shared.b64 _, [%0], %1;"::"r"((uint32_t)(a)),"r"((uint32_t)(tx)):"memory")
#define MB_WAIT(a,p) do{ uint32_t _m=(uint32_t)(a),_p=(uint32_t)(p),_d; \
    asm volatile("{\n\t.reg .pred q;\n\tmbarrier.try_wait.parity.acquire.cta.shared::cta.b64 q, [%1], %2;\n\tselp.b32 %0,1,0,q;\n\t}":"=r"(_d):"r"(_m),"r"(_p):"memory"); \
    if(!_d){ asm volatile("{\n\t.reg .pred P;\n\tWL_%=:\n\tmbarrier.try_wait.parity.acquire.cta.shared::cta.b64 P, [%0], %1, 0x989680;\n\t@P bra.uni WD_%=;\n\tbra.uni WL_%=;\n\tWD_%=:\n\t}"::"r"(_m),"r"(_p):"memory"); } }while(0)
#define FENCE_ASY() asm volatile("fence.proxy.async.shared::cta;":::"memory")

__device__ __forceinline__ void ldsm4(uint32_t* r, uint32_t addr){
    asm volatile("ldmatrix.sync.aligned.m8n8.x4.shared.b16 {%0,%1,%2,%3}, [%4];"
        : "=r"(r[0]),"=r"(r[1]),"=r"(r[2]),"=r"(r[3]) : "r"(addr));
}
__device__ __forceinline__ void mma16816(float* d, const uint32_t* a, const uint32_t* b){
    asm volatile("mma.sync.aligned.m16n8k16.row.col.f32.f16.f16.f32 "
        "{%0,%1,%2,%3}, {%4,%5,%6,%7}, {%8,%9}, {%0,%1,%2,%3};"
        : "+f"(d[0]),"+f"(d[1]),"+f"(d[2]),"+f"(d[3])
        : "r"(a[0]),"r"(a[1]),"r"(a[2]),"r"(a[3]), "r"(b[0]),"r"(b[1]));
}

// ---------------- fp32 -> fp16 hi/lo split into chunked layout ----------------
__global__ void split_kernel(const float* __restrict__ in,
                             unsigned short* __restrict__ hi,
                             unsigned short* __restrict__ lo, long long n4){
    long long i = (long long)blockIdx.x*256 + threadIdx.x;
    if (i >= n4) return;
    int m  = (int)(i >> 7);          // 128 float4 per row
    int k4 = (int)(i & 127);
    float4 v = reinterpret_cast<const float4*>(in)[i];
    float vs[4] = {v.x, v.y, v.z, v.w};
    unsigned short hb[4], lb[4];
#pragma unroll
    for (int c = 0; c < 4; c++){
        __half h = __float2half_rn(vs[c]);
        float r = vs[c] - __half2float(h);
        hb[c] = __half_as_ushort(h);
        lb[c] = __half_as_ushort(__float2half_rn(r));
    }
    uint2 H, L;
    H.x = hb[0] | ((uint32_t)hb[1] << 16);  H.y = hb[2] | ((uint32_t)hb[3] << 16);
    L.x = lb[0] | ((uint32_t)lb[1] << 16);  L.y = lb[2] | ((uint32_t)lb[3] << 16);
    size_t off = coff(m, k4 << 2);   // 8B-aligned; swizzle preserves 8B units
    *reinterpret_cast<uint2*>((char*)hi + off) = H;
    *reinterpret_cast<uint2*>((char*)lo + off) = L;
}

// ---------------- bias gather ----------------
__global__ void bias_gather_kernel(const float* __restrict__ rpb,
                                   const int* __restrict__ rel){
    int g = blockIdx.x*256 + threadIdx.x;
    if (g >= NHEAD*NN2) return;
    int h = g / NN2, p = g - h*NN2;
    g_bias[g] = rpb[rel[p]*NHEAD + h];
}

// ---------------- warp-MMA GEMM, bulk-DMA loads (R15 winner, frozen) ---------
#define NSTAGE 4
#define GEMM_SMEM (NSTAGE*16384 + 64)
#define NCHUNK 32

__global__ __launch_bounds__(256, 2)
void gemm_mma(const unsigned short* __restrict__ Ah, const unsigned short* __restrict__ Al,
              const unsigned short* __restrict__ Wh,
              const float* __restrict__ bias, float* __restrict__ C, int N, float alpha){
    extern __shared__ __align__(128) unsigned char dyn[];
    const uint32_t base = smem_u32(dyn);
    const uint32_t mb0  = base + NSTAGE*16384;          // 4 mbarriers, 8B apart

    const int tid = threadIdx.x, lane = tid & 31, wid = tid >> 5;
    const int wm = wid & 1, wn = wid >> 1;              // 2 x 4 warp grid
    const int m0 = blockIdx.y * 128, n0 = blockIdx.x * 128;

    const char* AP[2] = {(const char*)Ah, (const char*)Al};

    if (tid == 0){
#pragma unroll
        for (int s = 0; s < NSTAGE; s++) MB_INIT(mb0 + s*8, 1);
        FENCE_ASY();
    }
    __syncthreads();

    auto issue_chunk = [&](int t, int s){               // thread 0 only
        const char* srcA = AP[t >> 4] + ((size_t)blockIdx.y*16 + (t & 15))*8192;
        const char* srcW = (const char*)Wh + ((size_t)blockIdx.x*16 + (t & 15))*8192;
        uint32_t bar = mb0 + s*8;
        MB_EXPECT(bar, 16384u);
        CP_BULK(base + s*16384,        srcA, bar);
        CP_BULK(base + s*16384 + 8192, srcW, bar);
    };
    if (tid == 0){ issue_chunk(0,0); issue_chunk(1,1); issue_chunk(2,2); }

    // lane offsets within an 8KB block (64B rows, SW64 swizzle)
    uint32_t a_off[4], a_msk[4], b_off[2], b_msk[2];
#pragma unroll
    for (int mt = 0; mt < 4; mt++){
        int r = wm*64 + mt*16 + (lane & 15);
        a_off[mt] = (uint32_t)(r*64 + ((lane >> 4) & 1)*16);
        a_msk[mt] = (uint32_t)(((r >> 1) & 3) << 4);
    }
    {
        int g = lane >> 3;
#pragma unroll
        for (int q = 0; q < 2; q++){
            int r = wn*32 + (2*q + (g >> 1))*8 + (lane & 7);
            b_off[q] = (uint32_t)(r*64 + (g & 1)*16);
            b_msk[q] = (uint32_t)(((r >> 1) & 3) << 4);
        }
    }

    float acc[4][4][4];
#pragma unroll
    for (int i = 0; i < 4; i++)
#pragma unroll
        for (int j = 0; j < 4; j++)
#pragma unroll
            for (int k = 0; k < 4; k++) acc[i][j][k] = 0.f;

    for (int t = 0; t < NCHUNK; ++t){
        const int s = t & (NSTAGE - 1);
        const uint32_t ab = base + s*16384;
        const uint32_t wb = ab + 8192;
        MB_WAIT(mb0 + s*8, (t >> 2) & 1);

#pragma unroll
        for (int ks = 0; ks < 2; ks++){                  // 2 x k16 within BK=32
            uint32_t af[4][4], bf[2][4];
#pragma unroll
            for (int mt = 0; mt < 4; mt++)
                ldsm4(af[mt], ab + ((a_off[mt] + ks*32) ^ a_msk[mt]));
#pragma unroll
            for (int q = 0; q < 2; q++)
                ldsm4(bf[q],  wb + ((b_off[q] + ks*32) ^ b_msk[q]));
#pragma unroll
            for (int mt = 0; mt < 4; mt++){
                mma16816(acc[mt][0], af[mt], bf[0] + 0);
                mma16816(acc[mt][1], af[mt], bf[0] + 2);
                mma16816(acc[mt][2], af[mt], bf[1] + 0);
                mma16816(acc[mt][3], af[mt], bf[1] + 2);
            }
        }
        __syncthreads();                                 // all reads of stage (t+3)&3 done
        if (t + 3 < NCHUNK && tid == 0) issue_chunk(t + 3, (t + 3) & (NSTAGE - 1));
    }

    // epilogue
#pragma unroll
    for (int mt = 0; mt < 4; mt++){
#pragma unroll
        for (int nt = 0; nt < 4; nt++){
            int rg = m0 + wm*64 + mt*16 + (lane >> 2);
            int cg = n0 + wn*32 + nt*8 + 2*(lane & 3);
            float b0 = bias[cg], b1 = bias[cg + 1];
            float2 o0 = make_float2(alpha*(acc[mt][nt][0] + b0), alpha*(acc[mt][nt][1] + b1));
            float2 o1 = make_float2(alpha*(acc[mt][nt][2] + b0), alpha*(acc[mt][nt][3] + b1));
            *reinterpret_cast<float2*>(C + (size_t)rg*N + cg)       = o0;
            *reinterpret_cast<float2*>(C + (size_t)(rg + 8)*N + cg) = o1;
        }
    }
}

// ---------------- attention: R15 math, 256 threads (single-pass tiles) -------
#define QP 36
#define SP 56

__global__ __launch_bounds__(256)
void attn_kernel(){
    const int bh = blockIdx.x;
    const int h  = bh & (NHEAD-1);
    const int bt = bh >> 4;
    const int b  = bt >> 1;
    __shared__ __align__(16) float sq[52*QP], sk[52*QP], sv[52*QP], sS[52*SP];
    const int tid = threadIdx.x;

    for (int p = tid; p < 52*HDIM; p += 256){
        int i = p >> 5, d = p & 31;
        float qv = 0.f, kv = 0.f, vv = 0.f;
        if (i < NTOK){
            qv = g_q[(size_t)(b*NTOK+i)*CDIM + h*HDIM + d];
            const float* kvr = g_kv + (size_t)(bt*NTOK+i)*(2*CDIM) + h*HDIM + d;
            kv = kvr[0];
            vv = kvr[CDIM];
        }
        sq[i*QP+d] = qv;
        sk[i*QP+d] = kv;
        sv[i*QP+d] = vv;
    }
    __syncthreads();

    // scores + bias: 169 tiles <= 256 threads -> single pass
    const float* biasH = g_bias + h*NN2;
    for (int p = tid; p < 169; p += 256){
        int ti = p / 13, tj = p - ti*13;
        int i0 = ti*4, j0 = tj*4;
        float a[4][4] = {};
#pragma unroll
        for (int dd = 0; dd < 8; dd++){
            float4 qa[4], kb[4];
#pragma unroll
            for (int r = 0; r < 4; r++) qa[r] = *reinterpret_cast<const float4*>(&sq[(i0+r)*QP + dd*4]);
#pragma unroll
            for (int c = 0; c < 4; c++) kb[c] = *reinterpret_cast<const float4*>(&sk[(j0+c)*QP + dd*4]);
#pragma unroll
            for (int r = 0; r < 4; r++)
#pragma unroll
                for (int c = 0; c < 4; c++)
                    a[r][c] += qa[r].x*kb[c].x + qa[r].y*kb[c].y + qa[r].z*kb[c].z + qa[r].w*kb[c].w;
        }
#pragma unroll
        for (int r = 0; r < 4; r++)
#pragma unroll
            for (int c = 0; c < 4; c++){
                int i = i0 + r, j = j0 + c;
                float bv = (i < NTOK && j < NTOK) ? biasH[i*NTOK + j] : 0.f;
                sS[i*SP + j] = a[r][c] + bv;
            }
    }
    __syncthreads();

    // softmax: one warp per row, 8 warps
    const int warp = tid >> 5, lane = tid & 31;
    for (int i = warp; i < NTOK; i += 8){
        float* row = sS + i*SP;
        float x0 = row[lane];
        bool  v1 = (lane + 32) < NTOK;
        float x1 = v1 ? row[lane+32] : -3.402823466e38f;
        float m = fmaxf(x0, x1);
#pragma unroll
        for (int o = 16; o > 0; o >>= 1) m = fmaxf(m, __shfl_xor_sync(0xffffffffu, m, o));
        float e0 = __expf(x0 - m);
        float e1 = v1 ? __expf(x1 - m) : 0.f;
        float s = e0 + e1;
#pragma unroll
        for (int o = 16; o > 0; o >>= 1) s += __shfl_xor_sync(0xffffffffu, s, o);
        float inv = 1.0f / s;
        row[lane] = e0*inv;
        if (v1) row[lane+32] = e1*inv;
    }
    __syncthreads();

    // O = S @ v : 104 tiles <= 256 threads -> single pass
    for (int p = tid; p < 104; p += 256){
        int ti = p >> 3, td = p & 7;
        int i0 = ti*4, d0 = td*4;
        float a[4][4] = {};
        for (int m = 0; m < NTOK; m++){
            float4 vv = *reinterpret_cast<const float4*>(&sv[m*QP + d0]);
            float s0 = sS[(i0+0)*SP + m];
            float s1 = sS[(i0+1)*SP + m];
            float s2 = sS[(i0+2)*SP + m];
            float s3 = sS[(i0+3)*SP + m];
            a[0][0] += s0*vv.x; a[0][1] += s0*vv.y; a[0][2] += s0*vv.z; a[0][3] += s0*vv.w;
            a[1][0] += s1*vv.x; a[1][1] += s1*vv.y; a[1][2] += s1*vv.z; a[1][3] += s1*vv.w;
            a[2][0] += s2*vv.x; a[2][1] += s2*vv.y; a[2][2] += s2*vv.z; a[2][3] += s2*vv.w;
            a[3][0] += s3*vv.x; a[3][1] += s3*vv.y; a[3][2] += s3*vv.z; a[3][3] += s3*vv.w;
        }
#pragma unroll
        for (int r = 0; r < 4; r++){
            int i = i0 + r;
            if (i >= NTOK) break;
            int m = bt*NTOK + i;
            int k = h*HDIM + d0;
            unsigned short hb[4], lb[4];
#pragma unroll
            for (int c = 0; c < 4; c++){
                __half hh = __float2half_rn(a[r][c]);
                hb[c] = __half_as_ushort(hh);
                lb[c] = __half_as_ushort(__float2half_rn(a[r][c] - __half2float(hh)));
            }
            uint2 H, L;
            H.x = hb[0] | ((uint32_t)hb[1] << 16);  H.y = hb[2] | ((uint32_t)hb[3] << 16);
            L.x = lb[0] | ((uint32_t)lb[1] << 16);  L.y = lb[2] | ((uint32_t)lb[3] << 16);
            size_t off = coff(m, k);
            *reinterpret_cast<uint2*>((char*)g_oh + off) = H;
            *reinterpret_cast<uint2*>((char*)g_ol + off) = L;
        }
    }
}

// ---------------- launch ----------------
extern "C" void kernel_launch(void* const* d_in, const int* in_sizes, int n_in,
                              void* d_out, int out_size){
    const float* x      = (const float*)d_in[0];
    const float* memory = (const float*)d_in[1];
    const float* rpb    = (const float*)d_in[2];
    const float* q_w    = (const float*)d_in[3];
    const float* q_b    = (const float*)d_in[4];
    const float* kv_w   = (const float*)d_in[5];
    const float* kv_b   = (const float*)d_in[6];
    const float* proj_w = (const float*)d_in[7];
    const float* proj_b = (const float*)d_in[8];
    const int*   rel    = (const int*)d_in[9];
    float* out = (float*)d_out;

    unsigned short *xh,*xl,*mh,*ml,*oh,*ol,*qwh,*qwl,*kvwh,*kvwl,*pwh,*pwl;
    float *pq,*pkv;
    cudaGetSymbolAddress((void**)&xh,g_xh);     cudaGetSymbolAddress((void**)&xl,g_xl);
    cudaGetSymbolAddress((void**)&mh,g_mh);     cudaGetSymbolAddress((void**)&ml,g_ml);
    cudaGetSymbolAddress((void**)&oh,g_oh);     cudaGetSymbolAddress((void**)&ol,g_ol);
    cudaGetSymbolAddress((void**)&qwh,g_qwh);   cudaGetSymbolAddress((void**)&qwl,g_qwl);
    cudaGetSymbolAddress((void**)&kvwh,g_kvwh); cudaGetSymbolAddress((void**)&kvwl,g_kvwl);
    cudaGetSymbolAddress((void**)&pwh,g_pwh);   cudaGetSymbolAddress((void**)&pwl,g_pwl);
    cudaGetSymbolAddress((void**)&pq,g_q);      cudaGetSymbolAddress((void**)&pkv,g_kv);

    cudaFuncSetAttribute(gemm_mma, cudaFuncAttributeMaxDynamicSharedMemorySize, GEMM_SMEM);

    const float scale = 0.17677669529663687f;  // 32^-0.5
    long long n4x = (long long)BB*NTOK*CDIM/4;
    long long n4m = (long long)BB*TT*NTOK*CDIM/4;

    // Launch order keeps gemm_mma(KV) at slot #4 — the ncu window.
    split_kernel<<<(unsigned)((n4m+255)/256),256>>>(memory, mh, ml, n4m);        // #1
    split_kernel<<<(2*CDIM*CDIM/4+255)/256,256>>>(kv_w, kvwh, kvwl, 2*CDIM*CDIM/4); // #2
    split_kernel<<<(unsigned)((n4x+255)/256),256>>>(x, xh, xl, n4x);             // #3
    {   // #4 (PROFILED): KV = memory @ kv_w^T + kv_b   M=200704 N=1024
        dim3 g(2*CDIM/128, BB*TT*NTOK/128);
        gemm_mma<<<g, 256, GEMM_SMEM>>>(mh, ml, kvwh, kv_b, pkv, 2*CDIM, 1.0f);
    }
    split_kernel<<<(CDIM*CDIM/4+255)/256,256>>>(q_w, qwh, qwl, CDIM*CDIM/4);     // #5
    {   // #6: Q = scale*(x @ q_w^T + q_b)              M=100352 N=512
        dim3 g(CDIM/128, BB*NTOK/128);
        gemm_mma<<<g, 256, GEMM_SMEM>>>(xh, xl, qwh, q_b, pq, CDIM, scale);
    }
    split_kernel<<<(CDIM*CDIM/4+255)/256,256>>>(proj_w, pwh, pwl, CDIM*CDIM/4);  // #7
    bias_gather_kernel<<<(NHEAD*NN2 + 255)/256, 256>>>(rpb, rel);                // #8
    attn_kernel<<<BB*TT*NHEAD, 256>>>();                                         // #9
    {   // #10: out = attn @ proj_w^T + proj_b          M=200704 N=512
        dim3 g(CDIM/128, BB*TT*NTOK/128);
        gemm_mma<<<g, 256, GEMM_SMEM>>>(oh, ol, pwh, proj_b, out, CDIM, 1.0f);
    }
    (void)in_sizes; (void)n_in; (void)out_size;
}